// round 6
// baseline (speedup 1.0000x reference)
#include <cuda_runtime.h>
#include <cstdint>

#define T_C 4
#define N_C 20000
#define E_C 320000
#define FIN 12
#define EH 32
#define NH 64
#define GH 64

// ---------------- device scratch ----------------
__device__ float d_xenc[T_C * N_C * NH];
__device__ float d_xsA [T_C * N_C * NH];
__device__ float d_xsB [T_C * N_C * NH];
__device__ float d_nsx [T_C * N_C * NH];   // batched x_in ns contributions (ns|nr)
__device__ float d_ndx [T_C * N_C * NH];   // batched x_in node contributions
__device__ float d_nsf [N_C * NH];         // ns_full for current step
__device__ float d_acc [N_C * NH];         // sent|recv scatter accumulator
__device__ float d_einc0[(size_t)T_C * E_C * EH];  // layer0 general-path e_in contribs
__device__ float d_einc1[(size_t)T_C * E_C * EH];  // layer1 e_in contribs (from L0 tail)
__device__ float d_hec [(size_t)E_C * EH];         // h_e @ W_he carry
__device__ float d_degw[N_C];
__device__ float d_g[GH], d_gsave[GH];
__device__ float d_gce[EH];
__device__ float d_gcn[NH];
__device__ float d_esum[EH], d_xsum[NH];
__device__ float d_Pp[EH], d_Pm[EH];
__device__ int   d_fast0;

__device__ __forceinline__ float dot4(float4 v, float4 w) {
    return v.x * w.x + v.y * w.y + v.z * w.z + v.w * w.w;
}

// ---------------- small kernels ----------------

__global__ __launch_bounds__(256) void k_encode(const float* __restrict__ na,
                                                const float* __restrict__ W_ne,
                                                const float* __restrict__ b_ne,
                                                float* __restrict__ xenc) {
    __shared__ float sW[FIN * NH + NH];
    __shared__ float sna[4 * FIN];
    int tid = threadIdx.x;
    for (int i = tid; i < FIN * NH + NH; i += 256)
        sW[i] = (i < FIN * NH) ? W_ne[i] : b_ne[i - FIN * NH];
    int row0 = blockIdx.x * 4;
    if (tid < 4 * FIN) sna[tid] = na[row0 * FIN + tid];
    __syncthreads();
    int r = tid >> 6, j = tid & 63;
    float v = sW[FIN * NH + j];
#pragma unroll
    for (int k = 0; k < FIN; k++) v += sna[r * FIN + k] * sW[k * NH + j];
    xenc[(size_t)(row0 + r) * 64 + j] = fmaxf(v, 0.f);
}

__global__ void k_prep(const float* __restrict__ W_ee, const float* __restrict__ b_ee,
                       const float* __restrict__ W_eb) {
    int j = threadIdx.x;  // 32
    float pp = 0.f, pm = 0.f;
    bool ok = true;
#pragma unroll
    for (int k = 0; k < EH; k++) {
        float w = W_ee[k];
        pp += fmaxf(w, 0.f)  * W_eb[k * EH + j];
        pm += fmaxf(-w, 0.f) * W_eb[k * EH + j];
        if (b_ee[k] != 0.f) ok = false;
    }
    d_Pp[j] = pp; d_Pm[j] = pm;
    if (j == 0) d_fast0 = ok ? 1 : 0;
}

__global__ void k_ginit(const float* __restrict__ g0,
                        const float* __restrict__ W_eb, const float* __restrict__ b_eb,
                        const float* __restrict__ W_nb, const float* __restrict__ b_nb) {
    __shared__ float g[GH];
    int tid = threadIdx.x;  // 96
    if (tid < GH) { g[tid] = g0[tid]; d_g[tid] = g0[tid]; }
    __syncthreads();
    if (tid < EH) {
        float v = b_eb[tid];
#pragma unroll
        for (int k = 0; k < GH; k++) v += g[k] * W_eb[(320 + k) * EH + tid];
        d_gce[tid] = v;
    } else if (tid < 32 + NH) {
        int j = tid - 32;
        float v = b_nb[j];
#pragma unroll
        for (int k = 0; k < GH; k++) v += g[k] * W_nb[(192 + k) * NH + j];
        d_gcn[j] = v;
    }
}

__global__ void k_global(const float* __restrict__ W_gb, const float* __restrict__ b_gb,
                         const float* __restrict__ W_eb, const float* __restrict__ b_eb,
                         const float* __restrict__ W_nb, const float* __restrict__ b_nb,
                         int save) {
    __shared__ float gcat[160], gnew[GH];
    int tid = threadIdx.x;  // 256
    if (tid < 64) gcat[tid] = d_xsum[tid] * (1.0f / N_C);
    else if (tid < 96) gcat[tid] = d_esum[tid - 64] * (1.0f / E_C);
    else if (tid < 160) gcat[tid] = d_g[tid - 96];
    __syncthreads();
    if (tid < GH) {
        float v = b_gb[tid];
        for (int k = 0; k < 160; k++) v += gcat[k] * W_gb[k * GH + tid];
        gnew[tid] = fmaxf(v, 0.f);
    }
    __syncthreads();
    if (tid < GH) {
        d_g[tid] = gnew[tid];
        if (save) d_gsave[tid] = gnew[tid];
        d_xsum[tid] = 0.f;
    }
    if (tid < EH) d_esum[tid] = 0.f;
    if (tid < EH) {
        float v = b_eb[tid];
#pragma unroll
        for (int k = 0; k < GH; k++) v += gnew[k] * W_eb[(320 + k) * EH + tid];
        d_gce[tid] = v;
    } else if (tid < 32 + NH) {
        int j = tid - 32;
        float v = b_nb[j];
#pragma unroll
        for (int k = 0; k < GH; k++) v += gnew[k] * W_nb[(192 + k) * NH + j];
        d_gcn[j] = v;
    }
}

__global__ void k_degw(const int* __restrict__ eidx, const float* __restrict__ spL,
                       float* __restrict__ degw) {
    int i = blockIdx.x * 256 + threadIdx.x;
    if (i < E_C) atomicAdd(&degw[eidx[E_C + i]], spL[i]);
}

// ---------------- k_batch_pre: [nsx|ndx] = xall @ G, 4N rows, grid 2500 ----------------
__global__ __launch_bounds__(256) void k_batch_pre(const float* __restrict__ xall,
                                                   const float* __restrict__ W_eb,
                                                   const float* __restrict__ W_nb,
                                                   float* __restrict__ nsx,
                                                   float* __restrict__ ndx) {
    __shared__ float sWt[128 * 68];
    __shared__ float sv[32 * 68];
    int tid = threadIdx.x;
    for (int idx = tid; idx < 128 * 64; idx += 256) {
        int k = idx >> 7, j = idx & 127;
        float w = (j < 32) ? W_eb[(64 + k) * EH + j]
                : (j < 64) ? W_eb[(192 + k) * EH + (j - 32)]
                           : W_nb[k * NH + (j - 64)];
        sWt[j * 68 + k] = w;
    }
    int base = blockIdx.x * 32;
    for (int idx = tid; idx < 32 * 64; idx += 256) {
        int n = idx >> 6, c = idx & 63;
        sv[n * 68 + c] = xall[(size_t)(base + n) * 64 + c];
    }
    __syncthreads();
    int og = tid & 31, ng = tid >> 5;   // rows ng+8c, outs og+32d
    float acc[16];
#pragma unroll
    for (int i = 0; i < 16; i++) acc[i] = 0.f;
#pragma unroll
    for (int kq = 0; kq < 16; kq++) {
        float4 v[4], w[4];
#pragma unroll
        for (int c = 0; c < 4; c++) v[c] = *(const float4*)&sv[(ng + 8 * c) * 68 + 4 * kq];
#pragma unroll
        for (int d = 0; d < 4; d++) w[d] = *(const float4*)&sWt[(og + 32 * d) * 68 + 4 * kq];
#pragma unroll
        for (int c = 0; c < 4; c++)
#pragma unroll
            for (int d = 0; d < 4; d++) acc[c * 4 + d] += dot4(v[c], w[d]);
    }
#pragma unroll
    for (int c = 0; c < 4; c++) {
        size_t row = base + ng + 8 * c;
#pragma unroll
        for (int d = 0; d < 4; d++) {
            int jp = og + 32 * d;
            if (d < 2) nsx[row * 64 + jp] = acc[c * 4 + d];
            else       ndx[row * 64 + (jp - 64)] = acc[c * 4 + d];
        }
    }
}

// ---------------- k_einc_gen: general L0 edge-encoder path (skipped if fast) ----------------
__global__ __launch_bounds__(256) void k_einc_gen(const float* __restrict__ ea,
                                                  const float* __restrict__ W_ee,
                                                  const float* __restrict__ b_ee,
                                                  const float* __restrict__ W_eb,
                                                  float* __restrict__ einc0) {
    if (d_fast0) return;
    __shared__ float sWt[32 * 36];
    __shared__ float swee[32], sbee[32];
    int tid = threadIdx.x;
    for (int idx = tid; idx < 32 * 32; idx += 256) {
        int k = idx >> 5, j = idx & 31;
        sWt[j * 36 + k] = W_eb[k * EH + j];
    }
    if (tid < 32) { swee[tid] = W_ee[tid]; sbee[tid] = b_ee[tid]; }
    __syncthreads();
    int lane = tid & 31, wid = tid >> 5;
    int e0 = blockIdx.x * 128;
    for (int i = 0; i < 16; i++) {
        size_t e = e0 + wid * 16 + i;
        float a = ea[e];
        float acc = 0.f;
#pragma unroll
        for (int k = 0; k < 32; k++)
            acc += fmaxf(a * swee[k] + sbee[k], 0.f) * sWt[lane * 36 + k];
        einc0[e * 32 + lane] = acc;
    }
}

// ---------------- k_ns0: nsf = nsx[0]; acc = 0 ----------------
__global__ __launch_bounds__(256) void k_ns0(const float* __restrict__ nsx0,
                                             float* __restrict__ nsf,
                                             float* __restrict__ accb) {
    int i = blockIdx.x * 256 + threadIdx.x;
    nsf[i] = nsx0[i];
    accb[i] = 0.f;
}

// ---------------- k_edge6: sequential edge step ----------------
template <bool L0, bool HE, bool TAILH, bool TAILE>
__global__ __launch_bounds__(256) void k_edge6(const int* __restrict__ eidx,
                                               const float* __restrict__ ea_t,
                                               const float* __restrict__ einc_in,
                                               float* __restrict__ hec,
                                               float* __restrict__ eincout,
                                               const float* __restrict__ nsf,
                                               float* __restrict__ accbuf,
                                               const float* __restrict__ W_eb) {
    __shared__ float senew[128 * 36];
    __shared__ int   sidx[256];
    __shared__ float sred[256];
    __shared__ float sa[L0 ? 128 : 1];
    __shared__ float sWh[TAILH ? 32 * 36 : 1];
    __shared__ float sWe[TAILE ? 32 * 36 : 1];
    int tid = threadIdx.x;
    int e0b = blockIdx.x * 128;
    int fast = L0 ? d_fast0 : 0;
    if (tid < 128) {
        sidx[tid]       = eidx[e0b + tid];
        sidx[128 + tid] = eidx[E_C + e0b + tid];
        if (L0) sa[tid] = ea_t[e0b + tid];
    }
    if (TAILH)
        for (int idx = tid; idx < 32 * 32; idx += 256) {
            int k = idx >> 5, j = idx & 31;
            sWh[j * 36 + k] = W_eb[(32 + k) * EH + j];
        }
    if (TAILE)
        for (int idx = tid; idx < 32 * 32; idx += 256) {
            int k = idx >> 5, j = idx & 31;
            sWe[j * 36 + k] = W_eb[k * EH + j];
        }
    __syncthreads();
    int lane = tid & 31, wid = tid >> 5;
    float gce = d_gce[lane];
    float pp = 0.f, pm = 0.f;
    if (L0) { pp = d_Pp[lane]; pm = d_Pm[lane]; }
    float esum = 0.f;
#pragma unroll 4
    for (int i = 0; i < 16; i++) {
        int el = wid * 16 + i;
        size_t e = e0b + el;
        int s = sidx[el], r = sidx[128 + el];
        float b;
        if (L0 && fast) {
            float a = sa[el];
            b = (a >= 0.f) ? a * pp : -a * pm;
        } else {
            b = einc_in[e * 32 + lane];
        }
        if (HE) b += hec[e * 32 + lane];
        float en = fmaxf(b + nsf[(size_t)s * 64 + lane] + nsf[(size_t)r * 64 + 32 + lane] + gce, 0.f);
        senew[el * 36 + lane] = en;
        atomicAdd(&accbuf[(size_t)s * 64 + lane], en);
        atomicAdd(&accbuf[(size_t)r * 64 + 32 + lane], en);
        esum += en;
    }
    sred[wid * 32 + lane] = esum;
    __syncthreads();
    if (wid == 0) {
        float s2 = 0.f;
#pragma unroll
        for (int w = 0; w < 8; w++) s2 += sred[w * 32 + lane];
        atomicAdd(&d_esum[lane], s2);
    }
    if (TAILH || TAILE) {
        int og = tid & 7, eg = tid >> 3;  // rows eg+32c, outs og+8d
        if (TAILH) {
            float at[16];
#pragma unroll
            for (int i = 0; i < 16; i++) at[i] = 0.f;
#pragma unroll
            for (int kq = 0; kq < 8; kq++) {
                float4 v[4], w[4];
#pragma unroll
                for (int c = 0; c < 4; c++) v[c] = *(const float4*)&senew[(eg + 32 * c) * 36 + 4 * kq];
#pragma unroll
                for (int d = 0; d < 4; d++) w[d] = *(const float4*)&sWh[(og + 8 * d) * 36 + 4 * kq];
#pragma unroll
                for (int c = 0; c < 4; c++)
#pragma unroll
                    for (int d = 0; d < 4; d++) at[c * 4 + d] += dot4(v[c], w[d]);
            }
#pragma unroll
            for (int c = 0; c < 4; c++)
#pragma unroll
                for (int d = 0; d < 4; d++)
                    hec[(size_t)(e0b + eg + 32 * c) * 32 + og + 8 * d] = at[c * 4 + d];
        }
        if (TAILE) {
            float at[16];
#pragma unroll
            for (int i = 0; i < 16; i++) at[i] = 0.f;
#pragma unroll
            for (int kq = 0; kq < 8; kq++) {
                float4 v[4], w[4];
#pragma unroll
                for (int c = 0; c < 4; c++) v[c] = *(const float4*)&senew[(eg + 32 * c) * 36 + 4 * kq];
#pragma unroll
                for (int d = 0; d < 4; d++) w[d] = *(const float4*)&sWe[(og + 8 * d) * 36 + 4 * kq];
#pragma unroll
                for (int c = 0; c < 4; c++)
#pragma unroll
                    for (int d = 0; d < 4; d++) at[c * 4 + d] += dot4(v[c], w[d]);
            }
#pragma unroll
            for (int c = 0; c < 4; c++)
#pragma unroll
                for (int d = 0; d < 4; d++)
                    eincout[(size_t)(e0b + eg + 32 * c) * 32 + og + 8 * d] = at[c * 4 + d];
        }
    }
}

// ---------------- k_node6: x_new = relu(ndx + [h|acc]@W + gcn); td/sd fused ----------------
template <bool HASH, bool TD, bool SD>
__global__ __launch_bounds__(256) void k_node6(const float* __restrict__ ndx_t,
                                               const float* __restrict__ hx,
                                               const float* __restrict__ accb,
                                               const float* __restrict__ W_nb,
                                               float* __restrict__ xsout,
                                               float* __restrict__ tdout,
                                               float* __restrict__ sdout,
                                               const float* __restrict__ degw,
                                               const float* __restrict__ coeff) {
    constexpr int KW = HASH ? 132 : 68;
    constexpr int KQ = HASH ? 32 : 16;
    extern __shared__ float sm[];
    float* sWt  = sm;              // [64][KW]
    float* sv   = sm + 64 * KW;    // [32][KW]
    float* sred = sv + 32 * KW;    // [4][256]
    int tid = threadIdx.x;
    int base = blockIdx.x * 32;
    for (int idx = tid; idx < 64 * (HASH ? 128 : 64); idx += 256) {
        int k = idx >> 6, j = idx & 63;
        int row = HASH ? (64 + k) : (128 + k);
        sWt[j * KW + k] = W_nb[row * NH + j];
    }
    const float4* h4 = (const float4*)hx;
    const float4* a4 = (const float4*)accb;
    for (int idx = tid; idx < 32 * (HASH ? 32 : 16); idx += 256) {
        int n, q;
        if (HASH) { n = idx >> 5; q = idx & 31; }
        else      { n = idx >> 4; q = idx & 15; }
        float4 v;
        if (HASH) v = (q < 16) ? h4[(size_t)(base + n) * 16 + q]
                               : a4[(size_t)(base + n) * 16 + q - 16];
        else      v = a4[(size_t)(base + n) * 16 + q];
        *(float4*)&sv[n * KW + 4 * q] = v;
    }
    __syncthreads();
    int og = tid & 15, ng = tid >> 4;  // rows ng+16c (c 0..1), outs og+16d
    float acc[8];
#pragma unroll
    for (int i = 0; i < 8; i++) acc[i] = 0.f;
#pragma unroll 8
    for (int kq = 0; kq < KQ; kq++) {
        float4 v[2], w[4];
        v[0] = *(const float4*)&sv[ng * KW + 4 * kq];
        v[1] = *(const float4*)&sv[(ng + 16) * KW + 4 * kq];
#pragma unroll
        for (int d = 0; d < 4; d++) w[d] = *(const float4*)&sWt[(og + 16 * d) * KW + 4 * kq];
#pragma unroll
        for (int c = 0; c < 2; c++)
#pragma unroll
            for (int d = 0; d < 4; d++) acc[c * 4 + d] += dot4(v[c], w[d]);
    }
    float gA[4];
#pragma unroll
    for (int d = 0; d < 4; d++) gA[d] = d_gcn[og + 16 * d];
    float cw = SD ? coeff[0] : 0.f;
    float ps[4] = {0.f, 0.f, 0.f, 0.f};
#pragma unroll
    for (int c = 0; c < 2; c++) {
        size_t row = base + ng + 16 * c;
        float dg = SD ? degw[row] : 0.f;
#pragma unroll
        for (int d = 0; d < 4; d++) {
            int j = og + 16 * d;
            float x = fmaxf(acc[c * 4 + d] + ndx_t[row * 64 + j] + gA[d], 0.f);
            xsout[row * 64 + j] = x;
            if (TD) tdout[row * 64 + j] = HASH ? (x - sv[(ng + 16 * c) * KW + j]) : x;
            if (SD) sdout[row * 64 + j] = -cw * dg * x;
            ps[d] += x;
        }
    }
#pragma unroll
    for (int d = 0; d < 4; d++) sred[d * 256 + tid] = ps[d];
    __syncthreads();
    if (tid < 64) {
        int ogj = tid & 15, dj = tid >> 4;
        float s = 0.f;
#pragma unroll
        for (int g = 0; g < 16; g++) s += sred[dj * 256 + g * 16 + ogj];
        atomicAdd(&d_xsum[ogj + 16 * dj], s);
    }
}

// ---------------- k_nsh: nsf = nsx[t+1] + x_new @ W_h-parts ; acc = 0 ----------------
__global__ __launch_bounds__(256) void k_nsh(const float* __restrict__ xnew,
                                             const float* __restrict__ nsx1,
                                             const float* __restrict__ W_eb,
                                             float* __restrict__ nsf,
                                             float* __restrict__ accb) {
    __shared__ float sWt[64 * 68];
    __shared__ float sv[32 * 68];
    int tid = threadIdx.x;
    int base = blockIdx.x * 32;
    for (int idx = tid; idx < 64 * 64; idx += 256) {
        int k = idx >> 6, j = idx & 63;
        sWt[j * 68 + k] = (j < 32) ? W_eb[(128 + k) * EH + j]
                                   : W_eb[(256 + k) * EH + (j - 32)];
    }
    for (int idx = tid; idx < 32 * 64; idx += 256) {
        int n = idx >> 6, c = idx & 63;
        sv[n * 68 + c] = xnew[(size_t)(base + n) * 64 + c];
    }
    __syncthreads();
    int og = tid & 15, ng = tid >> 4;
    float acc[8];
#pragma unroll
    for (int i = 0; i < 8; i++) acc[i] = 0.f;
#pragma unroll
    for (int kq = 0; kq < 16; kq++) {
        float4 v[2], w[4];
        v[0] = *(const float4*)&sv[ng * 68 + 4 * kq];
        v[1] = *(const float4*)&sv[(ng + 16) * 68 + 4 * kq];
#pragma unroll
        for (int d = 0; d < 4; d++) w[d] = *(const float4*)&sWt[(og + 16 * d) * 68 + 4 * kq];
#pragma unroll
        for (int c = 0; c < 2; c++)
#pragma unroll
            for (int d = 0; d < 4; d++) acc[c * 4 + d] += dot4(v[c], w[d]);
    }
#pragma unroll
    for (int c = 0; c < 2; c++) {
        size_t row = base + ng + 16 * c;
#pragma unroll
        for (int d = 0; d < 4; d++) {
            int j = og + 16 * d;
            nsf[row * 64 + j] = acc[c * 4 + d] + nsx1[row * 64 + j];
            accb[row * 64 + j] = 0.f;
        }
    }
}

// ---------------- sder2 / resid / decode ----------------
__global__ __launch_bounds__(256) void k_sder2(const int* __restrict__ eidx,
                                               const float* __restrict__ spL,
                                               const float* __restrict__ coeff,
                                               const float* __restrict__ xs,
                                               float* __restrict__ sd) {
    int tid = threadIdx.x, lane = tid & 31, wid = tid >> 5;
    int e = blockIdx.x * 8 + wid;
    int s = eidx[e], r = eidx[E_C + e];
    float cw = coeff[0] * spL[e];
    size_t bs = (size_t)s * 64, br = (size_t)r * 64;
    atomicAdd(&sd[br + lane], cw * xs[bs + lane]);
    atomicAdd(&sd[br + 32 + lane], cw * xs[bs + 32 + lane]);
}

__global__ __launch_bounds__(256) void k_resid(float* __restrict__ a, const float* __restrict__ b) {
    int i = blockIdx.x * 256 + threadIdx.x;
    a[i] += b[i];
}

__global__ __launch_bounds__(256) void k_decode5(const float* __restrict__ xa,
                                                 const float* __restrict__ xb,
                                                 const float* __restrict__ W1,
                                                 const float* __restrict__ b1,
                                                 const float* __restrict__ W2,
                                                 const float* __restrict__ b2,
                                                 float* __restrict__ outn) {
    __shared__ float sWt[64 * 68];
    __shared__ float sv[64 * 68];
    __shared__ float sw2[NH];
    int tid = threadIdx.x;
    int base = blockIdx.x * 64;
    for (int idx = tid; idx < 64 * 64; idx += 256) {
        int j = idx >> 6, k = idx & 63;
        sWt[j * 68 + k] = W1[k * NH + j];
    }
    const float4* a4 = (const float4*)xa;
    const float4* b4 = (const float4*)xb;
    for (int idx = tid; idx < 64 * 16; idx += 256) {
        int n = idx >> 4, q = idx & 15;
        float4 va = a4[(size_t)(base + n) * 16 + q];
        float4 vb = b4[(size_t)(base + n) * 16 + q];
        va.x += vb.x; va.y += vb.y; va.z += vb.z; va.w += vb.w;
        *(float4*)&sv[n * 68 + 4 * q] = va;
    }
    if (tid < NH) sw2[tid] = W2[tid];
    __syncthreads();
    int og = tid & 15, ng = tid >> 4;
    float acc[16];
#pragma unroll
    for (int i = 0; i < 16; i++) acc[i] = 0.f;
#pragma unroll
    for (int kq = 0; kq < 16; kq++) {
        float4 v[4], w[4];
#pragma unroll
        for (int c = 0; c < 4; c++) v[c] = *(const float4*)&sv[(ng + 16 * c) * 68 + 4 * kq];
#pragma unroll
        for (int d = 0; d < 4; d++) w[d] = *(const float4*)&sWt[(og + 16 * d) * 68 + 4 * kq];
#pragma unroll
        for (int c = 0; c < 4; c++)
#pragma unroll
            for (int d = 0; d < 4; d++) acc[c * 4 + d] += dot4(v[c], w[d]);
    }
    float w2[4], bb[4];
#pragma unroll
    for (int d = 0; d < 4; d++) { w2[d] = sw2[og + 16 * d]; bb[d] = b1[og + 16 * d]; }
    float b20 = b2[0];
#pragma unroll
    for (int c = 0; c < 4; c++) {
        float p = 0.f;
#pragma unroll
        for (int d = 0; d < 4; d++) p += fmaxf(acc[c * 4 + d] + bb[d], 0.f) * w2[d];
        p += __shfl_down_sync(0xffffffffu, p, 8);
        p += __shfl_down_sync(0xffffffffu, p, 4);
        p += __shfl_down_sync(0xffffffffu, p, 2);
        p += __shfl_down_sync(0xffffffffu, p, 1);
        if (og == 0) outn[base + ng + 16 * c] = p + b20;
    }
}

// ---------------- host launcher ----------------
extern "C" void kernel_launch(void* const* d_in, const int* in_sizes, int n_in,
                              void* d_out, int out_size) {
    const float* node_attr  = (const float*)d_in[0];
    const float* edge_attr  = (const float*)d_in[1];
    const int*   edge_index = (const int*)  d_in[2];
    const float* spL        = (const float*)d_in[3];
    const float* gattr      = (const float*)d_in[4];
    const float* coeff      = (const float*)d_in[5];
    const float* W_ee = (const float*)d_in[6];
    const float* b_ee = (const float*)d_in[7];
    const float* W_ne = (const float*)d_in[8];
    const float* b_ne = (const float*)d_in[9];
    const float* W_eb = (const float*)d_in[10];
    const float* b_eb = (const float*)d_in[11];
    const float* W_nb = (const float*)d_in[12];
    const float* b_nb = (const float*)d_in[13];
    const float* W_gb = (const float*)d_in[14];
    const float* b_gb = (const float*)d_in[15];
    const float* W_nd1 = (const float*)d_in[16];
    const float* b_nd1 = (const float*)d_in[17];
    const float* W_nd2 = (const float*)d_in[18];
    const float* b_nd2 = (const float*)d_in[19];

    float* out    = (float*)d_out;
    float* out_td = out + (size_t)T_C * N_C;
    float* out_sd = out_td + (size_t)T_C * N_C * NH;

    float *xenc, *xsA, *xsB, *nsx, *ndx, *nsf, *acc, *einc0, *einc1, *hec;
    float *degw, *gsave, *esum, *xsum;
    cudaGetSymbolAddress((void**)&xenc, d_xenc);
    cudaGetSymbolAddress((void**)&xsA,  d_xsA);
    cudaGetSymbolAddress((void**)&xsB,  d_xsB);
    cudaGetSymbolAddress((void**)&nsx,  d_nsx);
    cudaGetSymbolAddress((void**)&ndx,  d_ndx);
    cudaGetSymbolAddress((void**)&nsf,  d_nsf);
    cudaGetSymbolAddress((void**)&acc,  d_acc);
    cudaGetSymbolAddress((void**)&einc0, d_einc0);
    cudaGetSymbolAddress((void**)&einc1, d_einc1);
    cudaGetSymbolAddress((void**)&hec,  d_hec);
    cudaGetSymbolAddress((void**)&degw, d_degw);
    cudaGetSymbolAddress((void**)&gsave, d_gsave);
    cudaGetSymbolAddress((void**)&esum, d_esum);
    cudaGetSymbolAddress((void**)&xsum, d_xsum);

    const int NODE_SMEM_H = (64 * 132 + 32 * 132 + 1024) * 4;  // 54784
    const int NODE_SMEM_L = (64 * 68 + 32 * 68 + 1024) * 4;    // 30208
    cudaFuncSetAttribute(k_node6<true,  false, false>, cudaFuncAttributeMaxDynamicSharedMemorySize, NODE_SMEM_H);
    cudaFuncSetAttribute(k_node6<false, false, false>, cudaFuncAttributeMaxDynamicSharedMemorySize, NODE_SMEM_L);
    cudaFuncSetAttribute(k_node6<true,  true,  true>,  cudaFuncAttributeMaxDynamicSharedMemorySize, NODE_SMEM_H);
    cudaFuncSetAttribute(k_node6<false, true,  true>,  cudaFuncAttributeMaxDynamicSharedMemorySize, NODE_SMEM_L);

    const int EGRID = E_C / 128;     // 2500
    const int NGRID = N_C / 32;      // 625
    const size_t NSZ = (size_t)N_C * NH;
    const size_t TSZ = (size_t)T_C * N_C * NH;

    cudaMemsetAsync(esum, 0, EH * sizeof(float));
    cudaMemsetAsync(xsum, 0, NH * sizeof(float));
    cudaMemsetAsync(degw, 0, N_C * sizeof(float));

    k_encode<<<(T_C * N_C) / 4, 256>>>(node_attr, W_ne, b_ne, xenc);
    k_prep<<<1, 32>>>(W_ee, b_ee, W_eb);
    k_degw<<<(E_C + 255) / 256, 256>>>(edge_index, spL, degw);

    // ================= layer 0 =================
    k_ginit<<<1, 96>>>(gattr, W_eb, b_eb, W_nb, b_nb);
    k_batch_pre<<<(T_C * N_C) / 32, 256>>>(xenc, W_eb, W_nb, nsx, ndx);
    k_einc_gen<<<(T_C * E_C) / 128, 256>>>(edge_attr, W_ee, b_ee, W_eb, einc0);
    k_ns0<<<NSZ / 256, 256>>>(nsx, nsf, acc);
    for (int t = 0; t < T_C; t++) {
        const float* einc_t = einc0 + (size_t)t * E_C * EH;
        float* einc1_t = einc1 + (size_t)t * E_C * EH;
        if (t == 0)
            k_edge6<true, false, true, true><<<EGRID, 256>>>(edge_index,
                edge_attr + (size_t)t * E_C, einc_t, hec, einc1_t, nsf, acc, W_eb);
        else if (t < 3)
            k_edge6<true, true, true, true><<<EGRID, 256>>>(edge_index,
                edge_attr + (size_t)t * E_C, einc_t, hec, einc1_t, nsf, acc, W_eb);
        else
            k_edge6<true, true, false, true><<<EGRID, 256>>>(edge_index,
                edge_attr + (size_t)t * E_C, einc_t, hec, einc1_t, nsf, acc, W_eb);
        float* xs_t = xsA + (size_t)t * NSZ;
        if (t == 0)
            k_node6<false, false, false><<<NGRID, 256, NODE_SMEM_L>>>(
                ndx + (size_t)t * NSZ, nullptr, acc, W_nb, xs_t, nullptr, nullptr, nullptr, nullptr);
        else
            k_node6<true, false, false><<<NGRID, 256, NODE_SMEM_H>>>(
                ndx + (size_t)t * NSZ, xsA + (size_t)(t - 1) * NSZ, acc, W_nb,
                xs_t, nullptr, nullptr, nullptr, nullptr);
        if (t < T_C - 1) {
            k_global<<<1, 256>>>(W_gb, b_gb, W_eb, b_eb, W_nb, b_nb, t == 0 ? 1 : 0);
            k_nsh<<<NGRID, 256>>>(xs_t, nsx + (size_t)(t + 1) * NSZ, W_eb, nsf, acc);
        }
    }

    k_resid<<<TSZ / 256, 256>>>(xsA, xenc);
    cudaMemsetAsync(esum, 0, EH * sizeof(float));
    cudaMemsetAsync(xsum, 0, NH * sizeof(float));

    // ================= layer 1 =================
    k_ginit<<<1, 96>>>(gsave, W_eb, b_eb, W_nb, b_nb);
    k_batch_pre<<<(T_C * N_C) / 32, 256>>>(xsA, W_eb, W_nb, nsx, ndx);
    k_ns0<<<NSZ / 256, 256>>>(nsx, nsf, acc);
    for (int t = 0; t < T_C; t++) {
        const float* einc_t = einc1 + (size_t)t * E_C * EH;
        if (t == 0)
            k_edge6<false, false, true, false><<<EGRID, 256>>>(edge_index,
                nullptr, einc_t, hec, nullptr, nsf, acc, W_eb);
        else if (t < 3)
            k_edge6<false, true, true, false><<<EGRID, 256>>>(edge_index,
                nullptr, einc_t, hec, nullptr, nsf, acc, W_eb);
        else
            k_edge6<false, true, false, false><<<EGRID, 256>>>(edge_index,
                nullptr, einc_t, hec, nullptr, nsf, acc, W_eb);
        float* xs_t = xsB + (size_t)t * NSZ;
        float* td_t = out_td + (size_t)t * NSZ;
        float* sd_t = out_sd + (size_t)t * NSZ;
        if (t == 0)
            k_node6<false, true, true><<<NGRID, 256, NODE_SMEM_L>>>(
                ndx + (size_t)t * NSZ, nullptr, acc, W_nb, xs_t, td_t, sd_t, degw, coeff);
        else
            k_node6<true, true, true><<<NGRID, 256, NODE_SMEM_H>>>(
                ndx + (size_t)t * NSZ, xsB + (size_t)(t - 1) * NSZ, acc, W_nb,
                xs_t, td_t, sd_t, degw, coeff);
        if (t < T_C - 1) {
            k_global<<<1, 256>>>(W_gb, b_gb, W_eb, b_eb, W_nb, b_nb, 0);
            k_nsh<<<NGRID, 256>>>(xs_t, nsx + (size_t)(t + 1) * NSZ, W_eb, nsf, acc);
        }
        k_sder2<<<E_C / 8, 256>>>(edge_index, spL, coeff, xs_t, sd_t);
    }

    k_decode5<<<(T_C * N_C) / 64, 256>>>(xsA, xsB, W_nd1, b_nd1, W_nd2, b_nd2, out);
}

// round 7
// speedup vs baseline: 1.0127x; 1.0127x over previous
#include <cuda_runtime.h>
#include <cstdint>

#define T_C 4
#define N_C 20000
#define E_C 320000
#define FIN 12
#define EH 32
#define NH 64
#define GH 64

// ---------------- device scratch ----------------
__device__ float d_xenc[T_C * N_C * NH];
__device__ float d_xsA [T_C * N_C * NH];
__device__ float d_xsB [T_C * N_C * NH];
__device__ float d_nsx [T_C * N_C * NH];
__device__ float d_ndx [T_C * N_C * NH];
__device__ float d_nsf [N_C * NH];
__device__ float d_acc [N_C * NH];
__device__ float d_einc0[(size_t)T_C * E_C * EH];
__device__ float d_einc1[(size_t)T_C * E_C * EH];
__device__ float d_hec [(size_t)E_C * EH];
__device__ float d_degw[N_C];
__device__ float d_g[GH], d_gsave[GH];
__device__ float d_gce[EH];
__device__ float d_gcn[NH];
__device__ float d_esum[EH], d_xsum[NH];
__device__ float d_Pp[EH], d_Pm[EH];
__device__ int   d_fast0;
__device__ int   d_ctr;

__device__ __forceinline__ float dot4(float4 v, float4 w) {
    return v.x * w.x + v.y * w.y + v.z * w.z + v.w * w.w;
}

// ---------------- small kernels ----------------

__global__ __launch_bounds__(256) void k_encode(const float* __restrict__ na,
                                                const float* __restrict__ W_ne,
                                                const float* __restrict__ b_ne,
                                                float* __restrict__ xenc) {
    __shared__ float sW[FIN * NH + NH];
    __shared__ float sna[4 * FIN];
    int tid = threadIdx.x;
    for (int i = tid; i < FIN * NH + NH; i += 256)
        sW[i] = (i < FIN * NH) ? W_ne[i] : b_ne[i - FIN * NH];
    int row0 = blockIdx.x * 4;
    if (tid < 4 * FIN) sna[tid] = na[row0 * FIN + tid];
    __syncthreads();
    int r = tid >> 6, j = tid & 63;
    float v = sW[FIN * NH + j];
#pragma unroll
    for (int k = 0; k < FIN; k++) v += sna[r * FIN + k] * sW[k * NH + j];
    xenc[(size_t)(row0 + r) * 64 + j] = fmaxf(v, 0.f);
}

__global__ void k_prep(const float* __restrict__ W_ee, const float* __restrict__ b_ee,
                       const float* __restrict__ W_eb) {
    int j = threadIdx.x;
    float pp = 0.f, pm = 0.f;
    bool ok = true;
#pragma unroll
    for (int k = 0; k < EH; k++) {
        float w = W_ee[k];
        pp += fmaxf(w, 0.f)  * W_eb[k * EH + j];
        pm += fmaxf(-w, 0.f) * W_eb[k * EH + j];
        if (b_ee[k] != 0.f) ok = false;
    }
    d_Pp[j] = pp; d_Pm[j] = pm;
    if (j == 0) d_fast0 = ok ? 1 : 0;
}

__global__ void k_ginit(const float* __restrict__ g0,
                        const float* __restrict__ W_eb, const float* __restrict__ b_eb,
                        const float* __restrict__ W_nb, const float* __restrict__ b_nb) {
    __shared__ float g[GH];
    int tid = threadIdx.x;  // 96
    if (tid < GH) { g[tid] = g0[tid]; d_g[tid] = g0[tid]; }
    __syncthreads();
    if (tid < EH) {
        float v = b_eb[tid];
#pragma unroll
        for (int k = 0; k < GH; k++) v += g[k] * W_eb[(320 + k) * EH + tid];
        d_gce[tid] = v;
    } else if (tid < 32 + NH) {
        int j = tid - 32;
        float v = b_nb[j];
#pragma unroll
        for (int k = 0; k < GH; k++) v += g[k] * W_nb[(192 + k) * NH + j];
        d_gcn[j] = v;
    }
}

__global__ void k_degw(const int* __restrict__ eidx, const float* __restrict__ spL,
                       float* __restrict__ degw) {
    int i = blockIdx.x * 256 + threadIdx.x;
    if (i < E_C) atomicAdd(&degw[eidx[E_C + i]], spL[i]);
}

// ---------------- batched x_in precompute (+residual fold, +nsf/acc init) ----------------
template <bool RESID, bool NSF>
__global__ __launch_bounds__(256) void k_batch_pre(float* __restrict__ xall,
                                                   const float* __restrict__ xenc,
                                                   const float* __restrict__ W_eb,
                                                   const float* __restrict__ W_nb,
                                                   float* __restrict__ nsx,
                                                   float* __restrict__ ndx,
                                                   float* __restrict__ nsf,
                                                   float* __restrict__ accz) {
    __shared__ float sWt[128 * 68];
    __shared__ float sv[32 * 68];
    int tid = threadIdx.x;
    for (int idx = tid; idx < 128 * 64; idx += 256) {
        int k = idx >> 7, j = idx & 127;
        float w = (j < 32) ? W_eb[(64 + k) * EH + j]
                : (j < 64) ? W_eb[(192 + k) * EH + (j - 32)]
                           : W_nb[k * NH + (j - 64)];
        sWt[j * 68 + k] = w;
    }
    int base = blockIdx.x * 32;
    for (int idx = tid; idx < 32 * 64; idx += 256) {
        int n = idx >> 6, c = idx & 63;
        size_t row = base + n;
        float v = xall[row * 64 + c];
        if (RESID) { v += xenc[row * 64 + c]; xall[row * 64 + c] = v; }
        sv[n * 68 + c] = v;
    }
    __syncthreads();
    bool donsf = NSF && (base < N_C);
    int og = tid & 31, ng = tid >> 5;
    float acc[16];
#pragma unroll
    for (int i = 0; i < 16; i++) acc[i] = 0.f;
#pragma unroll
    for (int kq = 0; kq < 16; kq++) {
        float4 v[4], w[4];
#pragma unroll
        for (int c = 0; c < 4; c++) v[c] = *(const float4*)&sv[(ng + 8 * c) * 68 + 4 * kq];
#pragma unroll
        for (int d = 0; d < 4; d++) w[d] = *(const float4*)&sWt[(og + 32 * d) * 68 + 4 * kq];
#pragma unroll
        for (int c = 0; c < 4; c++)
#pragma unroll
            for (int d = 0; d < 4; d++) acc[c * 4 + d] += dot4(v[c], w[d]);
    }
#pragma unroll
    for (int c = 0; c < 4; c++) {
        size_t row = base + ng + 8 * c;
#pragma unroll
        for (int d = 0; d < 4; d++) {
            int jp = og + 32 * d;
            if (d < 2) {
                nsx[row * 64 + jp] = acc[c * 4 + d];
                if (donsf) {
                    nsf[row * 64 + jp] = acc[c * 4 + d];
                    accz[row * 64 + jp] = 0.f;
                }
            } else {
                ndx[row * 64 + (jp - 64)] = acc[c * 4 + d];
            }
        }
    }
}

// ---------------- general L0 edge-encoder path (skipped if fast) ----------------
__global__ __launch_bounds__(256) void k_einc_gen(const float* __restrict__ ea,
                                                  const float* __restrict__ W_ee,
                                                  const float* __restrict__ b_ee,
                                                  const float* __restrict__ W_eb,
                                                  float* __restrict__ einc0) {
    if (d_fast0) return;
    __shared__ float sWt[32 * 36];
    __shared__ float swee[32], sbee[32];
    int tid = threadIdx.x;
    for (int idx = tid; idx < 32 * 32; idx += 256) {
        int k = idx >> 5, j = idx & 31;
        sWt[j * 36 + k] = W_eb[k * EH + j];
    }
    if (tid < 32) { swee[tid] = W_ee[tid]; sbee[tid] = b_ee[tid]; }
    __syncthreads();
    int lane = tid & 31, wid = tid >> 5;
    int e0 = blockIdx.x * 128;
    for (int i = 0; i < 16; i++) {
        size_t e = e0 + wid * 16 + i;
        float a = ea[e];
        float acc = 0.f;
#pragma unroll
        for (int k = 0; k < 32; k++)
            acc += fmaxf(a * swee[k] + sbee[k], 0.f) * sWt[lane * 36 + k];
        einc0[e * 32 + lane] = acc;
    }
}

// ---------------- edge step ----------------
template <bool L0, bool HE, bool TAILH, bool TAILE, bool SUM>
__global__ __launch_bounds__(256) void k_edge7(const int* __restrict__ eidx,
                                               const float* __restrict__ ea_t,
                                               const float* __restrict__ einc_in,
                                               float* __restrict__ hec,
                                               float* __restrict__ eincout,
                                               const float* __restrict__ nsf,
                                               float* __restrict__ accbuf,
                                               const float* __restrict__ W_eb) {
    __shared__ float senew[128 * 36];
    __shared__ int   sidx[256];
    __shared__ float sred[256];
    __shared__ float sa[L0 ? 128 : 1];
    __shared__ float sWh[TAILH ? 32 * 36 : 1];
    __shared__ float sWe[TAILE ? 32 * 36 : 1];
    int tid = threadIdx.x;
    int e0b = blockIdx.x * 128;
    int fast = L0 ? d_fast0 : 0;
    if (tid < 128) {
        sidx[tid]       = eidx[e0b + tid];
        sidx[128 + tid] = eidx[E_C + e0b + tid];
        if (L0) sa[tid] = ea_t[e0b + tid];
    }
    if (TAILH)
        for (int idx = tid; idx < 32 * 32; idx += 256) {
            int k = idx >> 5, j = idx & 31;
            sWh[j * 36 + k] = W_eb[(32 + k) * EH + j];
        }
    if (TAILE)
        for (int idx = tid; idx < 32 * 32; idx += 256) {
            int k = idx >> 5, j = idx & 31;
            sWe[j * 36 + k] = W_eb[k * EH + j];
        }
    __syncthreads();
    int lane = tid & 31, wid = tid >> 5;
    float gce = d_gce[lane];
    float pp = 0.f, pm = 0.f;
    if (L0) { pp = d_Pp[lane]; pm = d_Pm[lane]; }
    float esum = 0.f;
#pragma unroll 4
    for (int i = 0; i < 16; i++) {
        int el = wid * 16 + i;
        size_t e = e0b + el;
        int s = sidx[el], r = sidx[128 + el];
        float b;
        if (L0 && fast) {
            float a = sa[el];
            b = (a >= 0.f) ? a * pp : -a * pm;
        } else {
            b = einc_in[e * 32 + lane];
        }
        if (HE) b += hec[e * 32 + lane];
        float en = fmaxf(b + nsf[(size_t)s * 64 + lane] + nsf[(size_t)r * 64 + 32 + lane] + gce, 0.f);
        senew[el * 36 + lane] = en;
        atomicAdd(&accbuf[(size_t)s * 64 + lane], en);
        atomicAdd(&accbuf[(size_t)r * 64 + 32 + lane], en);
        if (SUM) esum += en;
    }
    if (SUM) {
        sred[wid * 32 + lane] = esum;
        __syncthreads();
        if (wid == 0) {
            float s2 = 0.f;
#pragma unroll
            for (int w = 0; w < 8; w++) s2 += sred[w * 32 + lane];
            atomicAdd(&d_esum[lane], s2);
        }
    }
    if (TAILH || TAILE) {
        if (!SUM) __syncthreads();
        int og = tid & 7, eg = tid >> 3;
        if (TAILH) {
            float at[16];
#pragma unroll
            for (int i = 0; i < 16; i++) at[i] = 0.f;
#pragma unroll
            for (int kq = 0; kq < 8; kq++) {
                float4 v[4], w[4];
#pragma unroll
                for (int c = 0; c < 4; c++) v[c] = *(const float4*)&senew[(eg + 32 * c) * 36 + 4 * kq];
#pragma unroll
                for (int d = 0; d < 4; d++) w[d] = *(const float4*)&sWh[(og + 8 * d) * 36 + 4 * kq];
#pragma unroll
                for (int c = 0; c < 4; c++)
#pragma unroll
                    for (int d = 0; d < 4; d++) at[c * 4 + d] += dot4(v[c], w[d]);
            }
#pragma unroll
            for (int c = 0; c < 4; c++)
#pragma unroll
                for (int d = 0; d < 4; d++)
                    hec[(size_t)(e0b + eg + 32 * c) * 32 + og + 8 * d] = at[c * 4 + d];
        }
        if (TAILE) {
            float at[16];
#pragma unroll
            for (int i = 0; i < 16; i++) at[i] = 0.f;
#pragma unroll
            for (int kq = 0; kq < 8; kq++) {
                float4 v[4], w[4];
#pragma unroll
                for (int c = 0; c < 4; c++) v[c] = *(const float4*)&senew[(eg + 32 * c) * 36 + 4 * kq];
#pragma unroll
                for (int d = 0; d < 4; d++) w[d] = *(const float4*)&sWe[(og + 8 * d) * 36 + 4 * kq];
#pragma unroll
                for (int c = 0; c < 4; c++)
#pragma unroll
                    for (int d = 0; d < 4; d++) at[c * 4 + d] += dot4(v[c], w[d]);
            }
#pragma unroll
            for (int c = 0; c < 4; c++)
#pragma unroll
                for (int d = 0; d < 4; d++)
                    eincout[(size_t)(e0b + eg + 32 * c) * 32 + og + 8 * d] = at[c * 4 + d];
        }
    }
}

// ---------------- fused node step: x_new (+td/sd) + nsh + global ----------------
template <bool HASH, bool TD, bool SD, bool NSH, bool GLOB>
__global__ __launch_bounds__(256) void k_node7(
    const float* __restrict__ ndx_t, const float* __restrict__ hx,
    const float* __restrict__ accb, const float* __restrict__ W_nb,
    float* __restrict__ xsout, float* __restrict__ tdout, float* __restrict__ sdout,
    const float* __restrict__ degw, const float* __restrict__ coeff,
    const float* __restrict__ nsx1, const float* __restrict__ W_eb,
    float* __restrict__ nsf, float* __restrict__ accz,
    const float* __restrict__ W_gb, const float* __restrict__ b_gb,
    const float* __restrict__ b_eb, const float* __restrict__ b_nb,
    int save) {
    constexpr int KW = HASH ? 132 : 68;
    constexpr int KQ = HASH ? 32 : 16;
    extern __shared__ float sm[];
    float* sWt  = sm;              // [64][KW]
    float* sv   = sm + 64 * KW;    // [32][KW]
    float* sred = sv + 32 * KW;    // [1024]
    __shared__ int slast;
    int tid = threadIdx.x;
    int base = blockIdx.x * 32;
    for (int idx = tid; idx < 64 * (HASH ? 128 : 64); idx += 256) {
        int k = idx >> 6, j = idx & 63;
        int row = HASH ? (64 + k) : (128 + k);
        sWt[j * KW + k] = W_nb[row * NH + j];
    }
    const float4* h4 = (const float4*)hx;
    const float4* a4 = (const float4*)accb;
    for (int idx = tid; idx < 32 * (HASH ? 32 : 16); idx += 256) {
        int n, q;
        if (HASH) { n = idx >> 5; q = idx & 31; }
        else      { n = idx >> 4; q = idx & 15; }
        float4 v;
        if (HASH) v = (q < 16) ? h4[(size_t)(base + n) * 16 + q]
                               : a4[(size_t)(base + n) * 16 + q - 16];
        else      v = a4[(size_t)(base + n) * 16 + q];
        *(float4*)&sv[n * KW + 4 * q] = v;
    }
    __syncthreads();
    int og = tid & 15, ng = tid >> 4;
    float acc[8];
#pragma unroll
    for (int i = 0; i < 8; i++) acc[i] = 0.f;
#pragma unroll 8
    for (int kq = 0; kq < KQ; kq++) {
        float4 v[2], w[4];
        v[0] = *(const float4*)&sv[ng * KW + 4 * kq];
        v[1] = *(const float4*)&sv[(ng + 16) * KW + 4 * kq];
#pragma unroll
        for (int d = 0; d < 4; d++) w[d] = *(const float4*)&sWt[(og + 16 * d) * KW + 4 * kq];
#pragma unroll
        for (int c = 0; c < 2; c++)
#pragma unroll
            for (int d = 0; d < 4; d++) acc[c * 4 + d] += dot4(v[c], w[d]);
    }
    float gA[4];
#pragma unroll
    for (int d = 0; d < 4; d++) gA[d] = d_gcn[og + 16 * d];
    float cw = SD ? coeff[0] : 0.f;
    float xv[8];
    float ps[4] = {0.f, 0.f, 0.f, 0.f};
#pragma unroll
    for (int c = 0; c < 2; c++) {
        size_t row = base + ng + 16 * c;
        float dg = SD ? degw[row] : 0.f;
#pragma unroll
        for (int d = 0; d < 4; d++) {
            int j = og + 16 * d;
            float x = fmaxf(acc[c * 4 + d] + ndx_t[row * 64 + j] + gA[d], 0.f);
            xv[c * 4 + d] = x;
            xsout[row * 64 + j] = x;
            if (TD) tdout[row * 64 + j] = HASH ? (x - sv[(ng + 16 * c) * KW + j]) : x;
            if (SD) sdout[row * 64 + j] = -cw * dg * x;
            ps[d] += x;
        }
    }
    if (GLOB) {
#pragma unroll
        for (int d = 0; d < 4; d++) sred[d * 256 + tid] = ps[d];
        __syncthreads();
        if (tid < 64) {
            int ogj = tid & 15, dj = tid >> 4;
            float s = 0.f;
#pragma unroll
            for (int g = 0; g < 16; g++) s += sred[dj * 256 + g * 16 + ogj];
            atomicAdd(&d_xsum[ogj + 16 * dj], s);
        }
    }
    if (NSH) {
        __syncthreads();
        for (int idx = tid; idx < 64 * 64; idx += 256) {
            int k = idx >> 6, j = idx & 63;
            sWt[j * 68 + k] = (j < 32) ? W_eb[(128 + k) * EH + j]
                                       : W_eb[(256 + k) * EH + (j - 32)];
        }
#pragma unroll
        for (int c = 0; c < 2; c++)
#pragma unroll
            for (int d = 0; d < 4; d++)
                sv[(ng + 16 * c) * 68 + og + 16 * d] = xv[c * 4 + d];
        __syncthreads();
        float a2[8];
#pragma unroll
        for (int i = 0; i < 8; i++) a2[i] = 0.f;
#pragma unroll
        for (int kq = 0; kq < 16; kq++) {
            float4 v[2], w[4];
            v[0] = *(const float4*)&sv[ng * 68 + 4 * kq];
            v[1] = *(const float4*)&sv[(ng + 16) * 68 + 4 * kq];
#pragma unroll
            for (int d = 0; d < 4; d++) w[d] = *(const float4*)&sWt[(og + 16 * d) * 68 + 4 * kq];
#pragma unroll
            for (int c = 0; c < 2; c++)
#pragma unroll
                for (int d = 0; d < 4; d++) a2[c * 4 + d] += dot4(v[c], w[d]);
        }
#pragma unroll
        for (int c = 0; c < 2; c++) {
            size_t row = base + ng + 16 * c;
#pragma unroll
            for (int d = 0; d < 4; d++) {
                int j = og + 16 * d;
                nsf[row * 64 + j] = a2[c * 4 + d] + nsx1[row * 64 + j];
                accz[row * 64 + j] = 0.f;
            }
        }
    }
    if (GLOB) {
        __syncthreads();
        __threadfence();
        if (tid == 0) slast = (atomicAdd(&d_ctr, 1) == (int)gridDim.x - 1);
        __syncthreads();
        if (slast) {
            float* gcat = sred;
            float* gnew = sred + 160;
            if (tid < 64) gcat[tid] = d_xsum[tid] * (1.0f / N_C);
            else if (tid < 96) gcat[tid] = d_esum[tid - 64] * (1.0f / E_C);
            else if (tid < 160) gcat[tid] = d_g[tid - 96];
            __syncthreads();
            if (tid < GH) {
                float v = b_gb[tid];
                for (int k = 0; k < 160; k++) v += gcat[k] * W_gb[k * GH + tid];
                gnew[tid] = fmaxf(v, 0.f);
            }
            __syncthreads();
            if (tid < GH) {
                d_g[tid] = gnew[tid];
                if (save) d_gsave[tid] = gnew[tid];
                d_xsum[tid] = 0.f;
            }
            if (tid < EH) {
                d_esum[tid] = 0.f;
                float v = b_eb[tid];
#pragma unroll
                for (int k = 0; k < GH; k++) v += gnew[k] * W_eb[(320 + k) * EH + tid];
                d_gce[tid] = v;
            } else if (tid < 32 + NH) {
                int j = tid - 32;
                float v = b_nb[j];
#pragma unroll
                for (int k = 0; k < GH; k++) v += gnew[k] * W_nb[(192 + k) * NH + j];
                d_gcn[j] = v;
            }
            if (tid == 0) d_ctr = 0;
        }
    }
}

// ---------------- all-steps sder ----------------
__global__ __launch_bounds__(256) void k_sder_all(const int* __restrict__ eidx,
                                                  const float* __restrict__ spL,
                                                  const float* __restrict__ coeff,
                                                  const float* __restrict__ xsB,
                                                  float* __restrict__ sd_out) {
    int lane = threadIdx.x & 31;
    int gid = blockIdx.x * 8 + (threadIdx.x >> 5);
    int t = gid / E_C;
    int e = gid - t * E_C;
    int s = eidx[e], r = eidx[E_C + e];
    float cw = coeff[0] * spL[e];
    const float* xs = xsB + (size_t)t * N_C * 64;
    float* sd = sd_out + (size_t)t * N_C * 64;
    size_t bs = (size_t)s * 64, br = (size_t)r * 64;
    atomicAdd(&sd[br + lane], cw * xs[bs + lane]);
    atomicAdd(&sd[br + 32 + lane], cw * xs[bs + 32 + lane]);
}

// ---------------- decode ----------------
__global__ __launch_bounds__(256) void k_decode5(const float* __restrict__ xa,
                                                 const float* __restrict__ xb,
                                                 const float* __restrict__ W1,
                                                 const float* __restrict__ b1,
                                                 const float* __restrict__ W2,
                                                 const float* __restrict__ b2,
                                                 float* __restrict__ outn) {
    __shared__ float sWt[64 * 68];
    __shared__ float sv[64 * 68];
    __shared__ float sw2[NH];
    int tid = threadIdx.x;
    int base = blockIdx.x * 64;
    for (int idx = tid; idx < 64 * 64; idx += 256) {
        int j = idx >> 6, k = idx & 63;
        sWt[j * 68 + k] = W1[k * NH + j];
    }
    const float4* a4 = (const float4*)xa;
    const float4* b4 = (const float4*)xb;
    for (int idx = tid; idx < 64 * 16; idx += 256) {
        int n = idx >> 4, q = idx & 15;
        float4 va = a4[(size_t)(base + n) * 16 + q];
        float4 vb = b4[(size_t)(base + n) * 16 + q];
        va.x += vb.x; va.y += vb.y; va.z += vb.z; va.w += vb.w;
        *(float4*)&sv[n * 68 + 4 * q] = va;
    }
    if (tid < NH) sw2[tid] = W2[tid];
    __syncthreads();
    int og = tid & 15, ng = tid >> 4;
    float acc[16];
#pragma unroll
    for (int i = 0; i < 16; i++) acc[i] = 0.f;
#pragma unroll
    for (int kq = 0; kq < 16; kq++) {
        float4 v[4], w[4];
#pragma unroll
        for (int c = 0; c < 4; c++) v[c] = *(const float4*)&sv[(ng + 16 * c) * 68 + 4 * kq];
#pragma unroll
        for (int d = 0; d < 4; d++) w[d] = *(const float4*)&sWt[(og + 16 * d) * 68 + 4 * kq];
#pragma unroll
        for (int c = 0; c < 4; c++)
#pragma unroll
            for (int d = 0; d < 4; d++) acc[c * 4 + d] += dot4(v[c], w[d]);
    }
    float w2[4], bb[4];
#pragma unroll
    for (int d = 0; d < 4; d++) { w2[d] = sw2[og + 16 * d]; bb[d] = b1[og + 16 * d]; }
    float b20 = b2[0];
#pragma unroll
    for (int c = 0; c < 4; c++) {
        float p = 0.f;
#pragma unroll
        for (int d = 0; d < 4; d++) p += fmaxf(acc[c * 4 + d] + bb[d], 0.f) * w2[d];
        p += __shfl_down_sync(0xffffffffu, p, 8);
        p += __shfl_down_sync(0xffffffffu, p, 4);
        p += __shfl_down_sync(0xffffffffu, p, 2);
        p += __shfl_down_sync(0xffffffffu, p, 1);
        if (og == 0) outn[base + ng + 16 * c] = p + b20;
    }
}

// ---------------- host launcher ----------------
extern "C" void kernel_launch(void* const* d_in, const int* in_sizes, int n_in,
                              void* d_out, int out_size) {
    const float* node_attr  = (const float*)d_in[0];
    const float* edge_attr  = (const float*)d_in[1];
    const int*   edge_index = (const int*)  d_in[2];
    const float* spL        = (const float*)d_in[3];
    const float* gattr      = (const float*)d_in[4];
    const float* coeff      = (const float*)d_in[5];
    const float* W_ee = (const float*)d_in[6];
    const float* b_ee = (const float*)d_in[7];
    const float* W_ne = (const float*)d_in[8];
    const float* b_ne = (const float*)d_in[9];
    const float* W_eb = (const float*)d_in[10];
    const float* b_eb = (const float*)d_in[11];
    const float* W_nb = (const float*)d_in[12];
    const float* b_nb = (const float*)d_in[13];
    const float* W_gb = (const float*)d_in[14];
    const float* b_gb = (const float*)d_in[15];
    const float* W_nd1 = (const float*)d_in[16];
    const float* b_nd1 = (const float*)d_in[17];
    const float* W_nd2 = (const float*)d_in[18];
    const float* b_nd2 = (const float*)d_in[19];

    float* out    = (float*)d_out;
    float* out_td = out + (size_t)T_C * N_C;
    float* out_sd = out_td + (size_t)T_C * N_C * NH;

    float *xenc, *xsA, *xsB, *nsx, *ndx, *nsf, *acc, *einc0, *einc1, *hec;
    float *degw, *gsave;
    cudaGetSymbolAddress((void**)&xenc, d_xenc);
    cudaGetSymbolAddress((void**)&xsA,  d_xsA);
    cudaGetSymbolAddress((void**)&xsB,  d_xsB);
    cudaGetSymbolAddress((void**)&nsx,  d_nsx);
    cudaGetSymbolAddress((void**)&ndx,  d_ndx);
    cudaGetSymbolAddress((void**)&nsf,  d_nsf);
    cudaGetSymbolAddress((void**)&acc,  d_acc);
    cudaGetSymbolAddress((void**)&einc0, d_einc0);
    cudaGetSymbolAddress((void**)&einc1, d_einc1);
    cudaGetSymbolAddress((void**)&hec,  d_hec);
    cudaGetSymbolAddress((void**)&degw, d_degw);
    cudaGetSymbolAddress((void**)&gsave, d_gsave);

    const int SM_H = (64 * 132 + 32 * 132 + 1024) * 4;  // 54784
    const int SM_L = (64 * 68 + 32 * 68 + 1024) * 4;    // 30208
    cudaFuncSetAttribute(k_node7<false, false, false, true,  true >, cudaFuncAttributeMaxDynamicSharedMemorySize, SM_L);
    cudaFuncSetAttribute(k_node7<true,  false, false, true,  true >, cudaFuncAttributeMaxDynamicSharedMemorySize, SM_H);
    cudaFuncSetAttribute(k_node7<true,  false, false, false, false>, cudaFuncAttributeMaxDynamicSharedMemorySize, SM_H);
    cudaFuncSetAttribute(k_node7<false, true,  true,  true,  true >, cudaFuncAttributeMaxDynamicSharedMemorySize, SM_L);
    cudaFuncSetAttribute(k_node7<true,  true,  true,  true,  true >, cudaFuncAttributeMaxDynamicSharedMemorySize, SM_H);
    cudaFuncSetAttribute(k_node7<true,  true,  true,  false, false>, cudaFuncAttributeMaxDynamicSharedMemorySize, SM_H);

    const int EGRID = E_C / 128;     // 2500
    const int NGRID = N_C / 32;      // 625
    const size_t NSZ = (size_t)N_C * NH;

    cudaMemsetAsync(degw, 0, N_C * sizeof(float));
    k_encode<<<(T_C * N_C) / 4, 256>>>(node_attr, W_ne, b_ne, xenc);
    k_prep<<<1, 32>>>(W_ee, b_ee, W_eb);
    k_degw<<<(E_C + 255) / 256, 256>>>(edge_index, spL, degw);

    // ================= layer 0 =================
    k_ginit<<<1, 96>>>(gattr, W_eb, b_eb, W_nb, b_nb);
    k_batch_pre<false, true><<<(T_C * N_C) / 32, 256>>>(xenc, nullptr, W_eb, W_nb, nsx, ndx, nsf, acc);
    k_einc_gen<<<(T_C * E_C) / 128, 256>>>(edge_attr, W_ee, b_ee, W_eb, einc0);
    for (int t = 0; t < T_C; t++) {
        const float* einc_t = einc0 + (size_t)t * E_C * EH;
        float* einc1_t = einc1 + (size_t)t * E_C * EH;
        const float* ea_t = edge_attr + (size_t)t * E_C;
        if (t == 0)
            k_edge7<true, false, true, true, true><<<EGRID, 256>>>(edge_index, ea_t, einc_t, hec, einc1_t, nsf, acc, W_eb);
        else if (t < 3)
            k_edge7<true, true, true, true, true><<<EGRID, 256>>>(edge_index, ea_t, einc_t, hec, einc1_t, nsf, acc, W_eb);
        else
            k_edge7<true, true, false, true, false><<<EGRID, 256>>>(edge_index, ea_t, einc_t, hec, einc1_t, nsf, acc, W_eb);
        float* xs_t = xsA + (size_t)t * NSZ;
        const float* nsx1 = nsx + (size_t)(t + 1) * NSZ;
        if (t == 0)
            k_node7<false, false, false, true, true><<<NGRID, 256, SM_L>>>(
                ndx + (size_t)t * NSZ, nullptr, acc, W_nb, xs_t, nullptr, nullptr, nullptr, nullptr,
                nsx1, W_eb, nsf, acc, W_gb, b_gb, b_eb, b_nb, 1);
        else if (t < 3)
            k_node7<true, false, false, true, true><<<NGRID, 256, SM_H>>>(
                ndx + (size_t)t * NSZ, xsA + (size_t)(t - 1) * NSZ, acc, W_nb, xs_t, nullptr, nullptr, nullptr, nullptr,
                nsx1, W_eb, nsf, acc, W_gb, b_gb, b_eb, b_nb, 0);
        else
            k_node7<true, false, false, false, false><<<NGRID, 256, SM_H>>>(
                ndx + (size_t)t * NSZ, xsA + (size_t)(t - 1) * NSZ, acc, W_nb, xs_t, nullptr, nullptr, nullptr, nullptr,
                nullptr, W_eb, nsf, acc, W_gb, b_gb, b_eb, b_nb, 0);
    }

    // ================= layer 1 =================
    k_ginit<<<1, 96>>>(gsave, W_eb, b_eb, W_nb, b_nb);
    k_batch_pre<true, true><<<(T_C * N_C) / 32, 256>>>(xsA, xenc, W_eb, W_nb, nsx, ndx, nsf, acc);
    for (int t = 0; t < T_C; t++) {
        const float* einc_t = einc1 + (size_t)t * E_C * EH;
        if (t == 0)
            k_edge7<false, false, true, false, true><<<EGRID, 256>>>(edge_index, nullptr, einc_t, hec, nullptr, nsf, acc, W_eb);
        else if (t < 3)
            k_edge7<false, true, true, false, true><<<EGRID, 256>>>(edge_index, nullptr, einc_t, hec, nullptr, nsf, acc, W_eb);
        else
            k_edge7<false, true, false, false, false><<<EGRID, 256>>>(edge_index, nullptr, einc_t, hec, nullptr, nsf, acc, W_eb);
        float* xs_t = xsB + (size_t)t * NSZ;
        float* td_t = out_td + (size_t)t * NSZ;
        float* sd_t = out_sd + (size_t)t * NSZ;
        const float* nsx1 = nsx + (size_t)(t + 1) * NSZ;
        if (t == 0)
            k_node7<false, true, true, true, true><<<NGRID, 256, SM_L>>>(
                ndx + (size_t)t * NSZ, nullptr, acc, W_nb, xs_t, td_t, sd_t, degw, coeff,
                nsx1, W_eb, nsf, acc, W_gb, b_gb, b_eb, b_nb, 0);
        else if (t < 3)
            k_node7<true, true, true, true, true><<<NGRID, 256, SM_H>>>(
                ndx + (size_t)t * NSZ, xsB + (size_t)(t - 1) * NSZ, acc, W_nb, xs_t, td_t, sd_t, degw, coeff,
                nsx1, W_eb, nsf, acc, W_gb, b_gb, b_eb, b_nb, 0);
        else
            k_node7<true, true, true, false, false><<<NGRID, 256, SM_H>>>(
                ndx + (size_t)t * NSZ, xsB + (size_t)(t - 1) * NSZ, acc, W_nb, xs_t, td_t, sd_t, degw, coeff,
                nullptr, W_eb, nsf, acc, W_gb, b_gb, b_eb, b_nb, 0);
    }

    k_sder_all<<<(T_C * E_C) / 8, 256>>>(edge_index, spL, coeff, xsB, out_sd);
    k_decode5<<<(T_C * N_C) / 64, 256>>>(xsA, xsB, W_nd1, b_nd1, W_nd2, b_nd2, out);
}